// round 13
// baseline (speedup 1.0000x reference)
#include <cuda_runtime.h>
#include <cuda_fp16.h>
#include <cstdint>
#include <cstddef>

#define B_DIM   8192
#define IN_DIM  4096
#define OUT_DIM 4096

// static device scratch (runtime allocation forbidden)
__device__ __align__(16) __half g_x16[(size_t)B_DIM * IN_DIM];
__device__ __align__(16) __half g_w16[(size_t)OUT_DIM * IN_DIM];
__device__ __align__(16) __half g_o16[(size_t)B_DIM * OUT_DIM];
__device__ __align__(16) float  g_sum[OUT_DIM];
__device__ __align__(16) float  g_sqs[OUT_DIM];
__device__ __align__(16) float  g_cA[OUT_DIM];
__device__ __align__(16) float  g_cB[OUT_DIM];

// ---------------- GEMM config ----------------
#define TM 128
#define TN 256
#define TK 64
#define NSTAGE 4
#define KITERS (IN_DIM / TK)        // 64
#define A_STG (TM * 128)            // 16 KB
#define B_STG (TN * 128)            // 32 KB
#define STG_BYTES (A_STG + B_STG)   // 48 KB
#define GEMM_SMEM (NSTAGE * STG_BYTES)  // 192 KB

__device__ __forceinline__ uint32_t smem_u32(const void* p) {
    uint32_t r;
    asm("{ .reg .u64 t; cvta.to.shared.u64 t, %1; cvt.u32.u64 %0, t; }" : "=r"(r) : "l"(p));
    return r;
}
__device__ __forceinline__ uint32_t sw128(uint32_t o) { return o ^ ((o >> 3) & 0x70); }

#define CP_ASYNC16(dst, src) \
    asm volatile("cp.async.cg.shared.global [%0], [%1], 16;" :: "r"(dst), "l"(src) : "memory")

__device__ __forceinline__ void ldsm_x4(uint32_t* r, uint32_t addr) {
    asm volatile("ldmatrix.sync.aligned.m8n8.x4.shared.b16 {%0,%1,%2,%3}, [%4];"
                 : "=r"(r[0]), "=r"(r[1]), "=r"(r[2]), "=r"(r[3]) : "r"(addr));
}
__device__ __forceinline__ void mma16816(float* c, const uint32_t* a, const uint32_t* b) {
    asm volatile("mma.sync.aligned.m16n8k16.row.col.f32.f16.f16.f32 "
                 "{%0,%1,%2,%3}, {%4,%5,%6,%7}, {%8,%9}, {%0,%1,%2,%3};"
                 : "+f"(c[0]), "+f"(c[1]), "+f"(c[2]), "+f"(c[3])
                 : "r"(a[0]), "r"(a[1]), "r"(a[2]), "r"(a[3]), "r"(b[0]), "r"(b[1]));
}

// ------------- merged conversion kernel (x -> fp16, W -> sign fp16) ---------
#define XBLOCKS 16384
#define WBLOCKS 8192
__global__ void cvt_all_kernel(const float* __restrict__ x, const float* __restrict__ w) {
    int b = blockIdx.x;
    if (b < XBLOCKS) {
        size_t i = (size_t)b * blockDim.x + threadIdx.x;
        const float4* p = (const float4*)x;
        float4 a = __ldcs(&p[2 * i]), c = __ldcs(&p[2 * i + 1]);
        __half2 h0 = __floats2half2_rn(a.x, a.y), h1 = __floats2half2_rn(a.z, a.w);
        __half2 h2 = __floats2half2_rn(c.x, c.y), h3 = __floats2half2_rn(c.z, c.w);
        uint4 o;
        o.x = *(uint32_t*)&h0; o.y = *(uint32_t*)&h1;
        o.z = *(uint32_t*)&h2; o.w = *(uint32_t*)&h3;
        ((uint4*)g_x16)[i] = o;
    } else {
        size_t i = (size_t)(b - XBLOCKS) * blockDim.x + threadIdx.x;
        if (i < OUT_DIM) { g_sum[i] = 0.f; g_sqs[i] = 0.f; }   // fused stats zeroing
        const float4* p = (const float4*)w;
        float4 a = __ldcs(&p[2 * i]), c = __ldcs(&p[2 * i + 1]);
        float s[8] = {a.x, a.y, a.z, a.w, c.x, c.y, c.z, c.w};
        __half h[8];
#pragma unroll
        for (int k = 0; k < 8; k++) {
            float v = s[k];
            h[k] = __float2half_rn((v > 0.f) ? 1.f : ((v < 0.f) ? -1.f : 0.f));
        }
        uint4 o;
        o.x = *(uint32_t*)&h[0]; o.y = *(uint32_t*)&h[2];
        o.z = *(uint32_t*)&h[4]; o.w = *(uint32_t*)&h[6];
        ((uint4*)g_w16)[i] = o;
    }
}

// --- GEMM: 128x256 CTA, 8 warps (64x64 tiles), cross-iter frag prefetch -----
__global__ void __launch_bounds__(256, 1) gemm_kernel() {
    extern __shared__ char smem[];
    uint32_t sb = smem_u32(smem);
    const int tid = threadIdx.x;
    const int wid = tid >> 5, lid = tid & 31;
    const int wm = wid >> 2, wn = wid & 3;        // 2 x 4 warp grid
    const int m0 = blockIdx.x * TM, n0 = blockIdx.y * TN;

    const __half* gA = g_x16 + (size_t)m0 * IN_DIM;
    const __half* gB = g_w16 + (size_t)n0 * IN_DIM;

    const int ldr = tid >> 3, ldq = tid & 7;

    // flat 12-chunk list per thread: j<4 -> A rows, j>=4 -> B rows
    auto issue_chunk = [&](int c, int j) {
        uint32_t base = sb + (uint32_t)(c & 3) * STG_BYTES;
        if (j < 4) {
            int r = ldr + j * 32;
            CP_ASYNC16(base + sw128((uint32_t)(r * 128 + ldq * 16)),
                       gA + (size_t)c * TK + (size_t)r * IN_DIM + ldq * 8);
        } else {
            int r = ldr + (j - 4) * 32;
            CP_ASYNC16(base + A_STG + sw128((uint32_t)(r * 128 + ldq * 16)),
                       gB + (size_t)c * TK + (size_t)r * IN_DIM + ldq * 8);
        }
    };

#pragma unroll
    for (int c = 0; c < 3; c++) {
#pragma unroll
        for (int j = 0; j < 12; j++) issue_chunk(c, j);
        asm volatile("cp.async.commit_group;" ::: "memory");
    }

    float acc[4][8][4];
#pragma unroll
    for (int mi = 0; mi < 4; mi++)
#pragma unroll
        for (int ni = 0; ni < 8; ni++)
#pragma unroll
            for (int q = 0; q < 4; q++) acc[mi][ni][q] = 0.f;

    const uint32_t a_row_l = (uint32_t)(wm * 64 + (lid & 15));
    const uint32_t a_col_l = (uint32_t)((lid >> 4) * 16);
    const uint32_t b_row_l = (uint32_t)(wn * 64 + (lid & 7) + ((lid >> 4) << 3));
    const uint32_t b_col_l = (uint32_t)(((lid >> 3) & 1) * 16);

    uint32_t aB[2][4][4], bB[2][4][4];

#define LOADFR(buf, ks, ab, bb) do {                                              \
    _Pragma("unroll")                                                             \
    for (int mi = 0; mi < 4; mi++)                                                \
        ldsm_x4(aB[buf][mi], (ab) + sw128((a_row_l + mi * 16) * 128 + a_col_l + (ks) * 32)); \
    _Pragma("unroll")                                                             \
    for (int nb = 0; nb < 4; nb++)                                                \
        ldsm_x4(bB[buf][nb], (bb) + sw128((b_row_l + nb * 16) * 128 + b_col_l + (ks) * 32)); \
} while (0)

#define MMABLK(buf) do {                                                          \
    _Pragma("unroll")                                                             \
    for (int mi = 0; mi < 4; mi++)                                                \
        _Pragma("unroll")                                                         \
        for (int nb = 0; nb < 4; nb++) {                                          \
            mma16816(acc[mi][2 * nb],     aB[buf][mi], &bB[buf][nb][0]);          \
            mma16816(acc[mi][2 * nb + 1], aB[buf][mi], &bB[buf][nb][2]);          \
        }                                                                         \
} while (0)

#define ISSUE3(j0) do {                                                           \
    if (pf) { issue_chunk(c + 3, (j0)); issue_chunk(c + 3, (j0) + 1); issue_chunk(c + 3, (j0) + 2); } \
} while (0)

    // prologue: retire stage 0's fill for ALL threads, make it visible, preload
    // ks=0 fragments. Invariant at each loop head: buf0 holds (c, ks0) frags
    // and stages c, c+1 are complete+visible (wait_group 2 after 3 commits).
    asm volatile("cp.async.wait_group 2;" ::: "memory");
    __syncthreads();
    LOADFR(0, 0, sb, sb + A_STG);

    for (int c = 0; c < KITERS; c++) {
        uint32_t ab = sb + (uint32_t)(c & 3) * STG_BYTES;
        uint32_t bb = ab + A_STG;
        const bool pf = (c + 3 < KITERS);

        LOADFR(1, 1, ab, bb); MMABLK(0); ISSUE3(0);
        LOADFR(0, 2, ab, bb); MMABLK(1); ISSUE3(3);
        LOADFR(1, 3, ab, bb); MMABLK(0); ISSUE3(6);
        ISSUE3(9);
        asm volatile("cp.async.commit_group;" ::: "memory");

        // retire so that stage c+1 is complete for EVERY thread, then barrier
        // makes it visible; preloading (c+1, ks0) frags is now race-free.
        asm volatile("cp.async.wait_group 2;" ::: "memory");
        __syncthreads();
        if (c + 1 < KITERS) {
            uint32_t an = sb + (uint32_t)((c + 1) & 3) * STG_BYTES;
            LOADFR(0, 0, an, an + A_STG);
        }
        MMABLK(1);   // last k16 of iter c, covers the prefetch latency
    }
#undef LOADFR
#undef MMABLK
#undef ISSUE3

    // ---- epilogue: fp16 store + fused column stats (fp32) ----
    const int trow = lid >> 2, tcol = (lid & 3) * 2;
#pragma unroll
    for (int mi = 0; mi < 4; mi++) {
#pragma unroll
        for (int ni = 0; ni < 8; ni++) {
            int row = m0 + wm * 64 + mi * 16 + trow;
            int col = n0 + wn * 64 + ni * 8 + tcol;
            __half* p = g_o16 + (size_t)row * OUT_DIM + col;
            *(__half2*)p = __floats2half2_rn(acc[mi][ni][0], acc[mi][ni][1]);
            *(__half2*)(p + 8 * OUT_DIM) = __floats2half2_rn(acc[mi][ni][2], acc[mi][ni][3]);
        }
    }
#pragma unroll
    for (int ni = 0; ni < 8; ni++) {
        float s0 = 0.f, s1 = 0.f, q0 = 0.f, q1 = 0.f;
#pragma unroll
        for (int mi = 0; mi < 4; mi++) {
            float v0 = acc[mi][ni][0], v1 = acc[mi][ni][1];
            float v2 = acc[mi][ni][2], v3 = acc[mi][ni][3];
            s0 += v0 + v2; s1 += v1 + v3;
            q0 += v0 * v0 + v2 * v2; q1 += v1 * v1 + v3 * v3;
        }
#pragma unroll
        for (int off = 4; off < 32; off <<= 1) {
            s0 += __shfl_xor_sync(0xffffffffu, s0, off);
            s1 += __shfl_xor_sync(0xffffffffu, s1, off);
            q0 += __shfl_xor_sync(0xffffffffu, q0, off);
            q1 += __shfl_xor_sync(0xffffffffu, q1, off);
        }
        if (trow == 0) {
            int col = n0 + wn * 64 + ni * 8 + tcol;
            atomicAdd(&g_sum[col], s0);
            atomicAdd(&g_sum[col + 1], s1);
            atomicAdd(&g_sqs[col], q0);
            atomicAdd(&g_sqs[col + 1], q1);
        }
    }
}

// ---------------- BatchNorm tail ----------------
__global__ void coef_kernel(const float* __restrict__ gamma, const float* __restrict__ beta) {
    int c = blockIdx.x * 256 + threadIdx.x;
    float mu = g_sum[c] * (1.f / B_DIM);
    float var = g_sqs[c] * (1.f / B_DIM) - mu * mu;
    float a = gamma[c] * rsqrtf(var + 1e-5f);
    g_cA[c] = a;
    g_cB[c] = beta[c] - a * mu;
}

// norm: 2 x uint4 (16 halves) per thread, streaming hints
__global__ void norm_kernel(float* __restrict__ out) {
    size_t i0 = 2 * ((size_t)blockIdx.x * blockDim.x + threadIdx.x);
#pragma unroll
    for (int u = 0; u < 2; u++) {
        size_t i = i0 + u;
        int col = (int)((i * 8) & (OUT_DIM - 1));
        uint4 v = __ldcs(&((const uint4*)g_o16)[i]);
        float4 a0 = __ldg((const float4*)&g_cA[col]);
        float4 a1 = __ldg((const float4*)&g_cA[col + 4]);
        float4 b0 = __ldg((const float4*)&g_cB[col]);
        float4 b1 = __ldg((const float4*)&g_cB[col + 4]);
        float2 f0 = __half22float2(*(__half2*)&v.x);
        float2 f1 = __half22float2(*(__half2*)&v.y);
        float2 f2 = __half22float2(*(__half2*)&v.z);
        float2 f3 = __half22float2(*(__half2*)&v.w);
        float4 r0, r1;
        r0.x = fmaf(a0.x, f0.x, b0.x); r0.y = fmaf(a0.y, f0.y, b0.y);
        r0.z = fmaf(a0.z, f1.x, b0.z); r0.w = fmaf(a0.w, f1.y, b0.w);
        r1.x = fmaf(a1.x, f2.x, b1.x); r1.y = fmaf(a1.y, f2.y, b1.y);
        r1.z = fmaf(a1.z, f3.x, b1.z); r1.w = fmaf(a1.w, f3.y, b1.w);
        __stcs(&((float4*)out)[2 * i],     r0);
        __stcs(&((float4*)out)[2 * i + 1], r1);
    }
}

extern "C" void kernel_launch(void* const* d_in, const int* in_sizes, int n_in,
                              void* d_out, int out_size) {
    (void)in_sizes; (void)n_in; (void)out_size;
    const float* x     = (const float*)d_in[0];
    const float* w     = (const float*)d_in[1];
    const float* gamma = (const float*)d_in[3];
    const float* beta  = (const float*)d_in[4];
    float* out = (float*)d_out;

    cudaFuncSetAttribute(gemm_kernel, cudaFuncAttributeMaxDynamicSharedMemorySize, GEMM_SMEM);

    cvt_all_kernel<<<XBLOCKS + WBLOCKS, 256>>>(x, w);
    gemm_kernel<<<dim3(B_DIM / TM, OUT_DIM / TN), 256, GEMM_SMEM>>>();
    coef_kernel<<<16, 256>>>(gamma, beta);
    norm_kernel<<<8192, 256>>>(out);
}

// round 14
// speedup vs baseline: 1.0289x; 1.0289x over previous
#include <cuda_runtime.h>
#include <cuda_fp16.h>
#include <cstdint>
#include <cstddef>

#define B_DIM   8192
#define IN_DIM  4096
#define OUT_DIM 4096

// static device scratch (runtime allocation forbidden)
__device__ __align__(16) __half g_x16[(size_t)B_DIM * IN_DIM];
__device__ __align__(16) __half g_w16[(size_t)OUT_DIM * IN_DIM];
__device__ __align__(16) __half g_o16[(size_t)B_DIM * OUT_DIM];
__device__ __align__(16) float  g_sum[OUT_DIM];
__device__ __align__(16) float  g_sqs[OUT_DIM];
__device__ __align__(16) float  g_cA[OUT_DIM];
__device__ __align__(16) float  g_cB[OUT_DIM];

// ---------------- GEMM config ----------------
#define TM 128
#define TN 256
#define TK 64
#define NSTAGE 4
#define KITERS (IN_DIM / TK)        // 64
#define A_STG (TM * 128)            // 16 KB
#define B_STG (TN * 128)            // 32 KB
#define STG_BYTES (A_STG + B_STG)   // 48 KB
#define GEMM_SMEM (NSTAGE * STG_BYTES)  // 192 KB

__device__ __forceinline__ uint32_t smem_u32(const void* p) {
    uint32_t r;
    asm("{ .reg .u64 t; cvta.to.shared.u64 t, %1; cvt.u32.u64 %0, t; }" : "=r"(r) : "l"(p));
    return r;
}
__device__ __forceinline__ uint32_t sw128(uint32_t o) { return o ^ ((o >> 3) & 0x70); }

#define CP_ASYNC16(dst, src) \
    asm volatile("cp.async.cg.shared.global [%0], [%1], 16;" :: "r"(dst), "l"(src) : "memory")

__device__ __forceinline__ void ldsm_x4(uint32_t* r, uint32_t addr) {
    asm volatile("ldmatrix.sync.aligned.m8n8.x4.shared.b16 {%0,%1,%2,%3}, [%4];"
                 : "=r"(r[0]), "=r"(r[1]), "=r"(r[2]), "=r"(r[3]) : "r"(addr));
}
__device__ __forceinline__ void mma16816(float* c, const uint32_t* a, const uint32_t* b) {
    asm volatile("mma.sync.aligned.m16n8k16.row.col.f32.f16.f16.f32 "
                 "{%0,%1,%2,%3}, {%4,%5,%6,%7}, {%8,%9}, {%0,%1,%2,%3};"
                 : "+f"(c[0]), "+f"(c[1]), "+f"(c[2]), "+f"(c[3])
                 : "r"(a[0]), "r"(a[1]), "r"(a[2]), "r"(a[3]), "r"(b[0]), "r"(b[1]));
}

// ------------- merged conversion kernel (x -> fp16, W -> sign fp16) ---------
#define XBLOCKS 16384
#define WBLOCKS 8192
__global__ void cvt_all_kernel(const float* __restrict__ x, const float* __restrict__ w) {
    int b = blockIdx.x;
    if (b < XBLOCKS) {
        size_t i = (size_t)b * blockDim.x + threadIdx.x;
        const float4* p = (const float4*)x;
        float4 a = __ldcs(&p[2 * i]), c = __ldcs(&p[2 * i + 1]);
        __half2 h0 = __floats2half2_rn(a.x, a.y), h1 = __floats2half2_rn(a.z, a.w);
        __half2 h2 = __floats2half2_rn(c.x, c.y), h3 = __floats2half2_rn(c.z, c.w);
        uint4 o;
        o.x = *(uint32_t*)&h0; o.y = *(uint32_t*)&h1;
        o.z = *(uint32_t*)&h2; o.w = *(uint32_t*)&h3;
        ((uint4*)g_x16)[i] = o;
    } else {
        size_t i = (size_t)(b - XBLOCKS) * blockDim.x + threadIdx.x;
        if (i < OUT_DIM) { g_sum[i] = 0.f; g_sqs[i] = 0.f; }   // fused stats zeroing
        const float4* p = (const float4*)w;
        float4 a = __ldcs(&p[2 * i]), c = __ldcs(&p[2 * i + 1]);
        float s[8] = {a.x, a.y, a.z, a.w, c.x, c.y, c.z, c.w};
        __half h[8];
#pragma unroll
        for (int k = 0; k < 8; k++) {
            float v = s[k];
            h[k] = __float2half_rn((v > 0.f) ? 1.f : ((v < 0.f) ? -1.f : 0.f));
        }
        uint4 o;
        o.x = *(uint32_t*)&h[0]; o.y = *(uint32_t*)&h[2];
        o.z = *(uint32_t*)&h[4]; o.w = *(uint32_t*)&h[6];
        ((uint4*)g_w16)[i] = o;
    }
}

// --- GEMM: 128x256 CTA, 8 warps (64x64 tiles), cross-iter frag prefetch -----
__global__ void __launch_bounds__(256, 1) gemm_kernel() {
    extern __shared__ char smem[];
    uint32_t sb = smem_u32(smem);
    const int tid = threadIdx.x;
    const int wid = tid >> 5, lid = tid & 31;
    const int wm = wid >> 2, wn = wid & 3;        // 2 x 4 warp grid
    const int m0 = blockIdx.x * TM, n0 = blockIdx.y * TN;

    const __half* gA = g_x16 + (size_t)m0 * IN_DIM;
    const __half* gB = g_w16 + (size_t)n0 * IN_DIM;

    const int ldr = tid >> 3, ldq = tid & 7;

    // flat 12-chunk list per thread: j<4 -> A rows, j>=4 -> B rows
    auto issue_chunk = [&](int c, int j) {
        uint32_t base = sb + (uint32_t)(c & 3) * STG_BYTES;
        if (j < 4) {
            int r = ldr + j * 32;
            CP_ASYNC16(base + sw128((uint32_t)(r * 128 + ldq * 16)),
                       gA + (size_t)c * TK + (size_t)r * IN_DIM + ldq * 8);
        } else {
            int r = ldr + (j - 4) * 32;
            CP_ASYNC16(base + A_STG + sw128((uint32_t)(r * 128 + ldq * 16)),
                       gB + (size_t)c * TK + (size_t)r * IN_DIM + ldq * 8);
        }
    };

#pragma unroll
    for (int c = 0; c < 3; c++) {
#pragma unroll
        for (int j = 0; j < 12; j++) issue_chunk(c, j);
        asm volatile("cp.async.commit_group;" ::: "memory");
    }

    float acc[4][8][4];
#pragma unroll
    for (int mi = 0; mi < 4; mi++)
#pragma unroll
        for (int ni = 0; ni < 8; ni++)
#pragma unroll
            for (int q = 0; q < 4; q++) acc[mi][ni][q] = 0.f;

    const uint32_t a_row_l = (uint32_t)(wm * 64 + (lid & 15));
    const uint32_t a_col_l = (uint32_t)((lid >> 4) * 16);
    const uint32_t b_row_l = (uint32_t)(wn * 64 + (lid & 7) + ((lid >> 4) << 3));
    const uint32_t b_col_l = (uint32_t)(((lid >> 3) & 1) * 16);

    uint32_t aB[2][4][4], bB[2][4][4];

#define LOADFR(buf, ks, ab, bb) do {                                              \
    _Pragma("unroll")                                                             \
    for (int mi = 0; mi < 4; mi++)                                                \
        ldsm_x4(aB[buf][mi], (ab) + sw128((a_row_l + mi * 16) * 128 + a_col_l + (ks) * 32)); \
    _Pragma("unroll")                                                             \
    for (int nb = 0; nb < 4; nb++)                                                \
        ldsm_x4(bB[buf][nb], (bb) + sw128((b_row_l + nb * 16) * 128 + b_col_l + (ks) * 32)); \
} while (0)

#define MMABLK(buf) do {                                                          \
    _Pragma("unroll")                                                             \
    for (int mi = 0; mi < 4; mi++)                                                \
        _Pragma("unroll")                                                         \
        for (int nb = 0; nb < 4; nb++) {                                          \
            mma16816(acc[mi][2 * nb],     aB[buf][mi], &bB[buf][nb][0]);          \
            mma16816(acc[mi][2 * nb + 1], aB[buf][mi], &bB[buf][nb][2]);          \
        }                                                                         \
} while (0)

#define ISSUE3(j0) do {                                                           \
    if (pf) { issue_chunk(c + 3, (j0)); issue_chunk(c + 3, (j0) + 1); issue_chunk(c + 3, (j0) + 2); } \
} while (0)

    // prologue: retire stage 0's fill for ALL threads, make it visible, preload
    // ks=0 fragments. Invariant at each loop head: buf0 holds (c, ks0) frags
    // and stages c, c+1 are complete+visible (wait_group 2 after 3 commits).
    asm volatile("cp.async.wait_group 2;" ::: "memory");
    __syncthreads();
    LOADFR(0, 0, sb, sb + A_STG);

    for (int c = 0; c < KITERS; c++) {
        uint32_t ab = sb + (uint32_t)(c & 3) * STG_BYTES;
        uint32_t bb = ab + A_STG;
        const bool pf = (c + 3 < KITERS);

        LOADFR(1, 1, ab, bb); MMABLK(0); ISSUE3(0);
        LOADFR(0, 2, ab, bb); MMABLK(1); ISSUE3(3);
        LOADFR(1, 3, ab, bb); MMABLK(0); ISSUE3(6);
        ISSUE3(9);
        asm volatile("cp.async.commit_group;" ::: "memory");

        // retire so that stage c+1 is complete for EVERY thread, then barrier
        // makes it visible; preloading (c+1, ks0) frags is now race-free.
        asm volatile("cp.async.wait_group 2;" ::: "memory");
        __syncthreads();
        if (c + 1 < KITERS) {
            uint32_t an = sb + (uint32_t)((c + 1) & 3) * STG_BYTES;
            LOADFR(0, 0, an, an + A_STG);
        }
        MMABLK(1);   // last k16 of iter c, covers the prefetch latency
    }
#undef LOADFR
#undef MMABLK
#undef ISSUE3

    // ---- epilogue: fp16 store + fused column stats (fp32) ----
    const int trow = lid >> 2, tcol = (lid & 3) * 2;
#pragma unroll
    for (int mi = 0; mi < 4; mi++) {
#pragma unroll
        for (int ni = 0; ni < 8; ni++) {
            int row = m0 + wm * 64 + mi * 16 + trow;
            int col = n0 + wn * 64 + ni * 8 + tcol;
            __half* p = g_o16 + (size_t)row * OUT_DIM + col;
            *(__half2*)p = __floats2half2_rn(acc[mi][ni][0], acc[mi][ni][1]);
            *(__half2*)(p + 8 * OUT_DIM) = __floats2half2_rn(acc[mi][ni][2], acc[mi][ni][3]);
        }
    }
#pragma unroll
    for (int ni = 0; ni < 8; ni++) {
        float s0 = 0.f, s1 = 0.f, q0 = 0.f, q1 = 0.f;
#pragma unroll
        for (int mi = 0; mi < 4; mi++) {
            float v0 = acc[mi][ni][0], v1 = acc[mi][ni][1];
            float v2 = acc[mi][ni][2], v3 = acc[mi][ni][3];
            s0 += v0 + v2; s1 += v1 + v3;
            q0 += v0 * v0 + v2 * v2; q1 += v1 * v1 + v3 * v3;
        }
#pragma unroll
        for (int off = 4; off < 32; off <<= 1) {
            s0 += __shfl_xor_sync(0xffffffffu, s0, off);
            s1 += __shfl_xor_sync(0xffffffffu, s1, off);
            q0 += __shfl_xor_sync(0xffffffffu, q0, off);
            q1 += __shfl_xor_sync(0xffffffffu, q1, off);
        }
        if (trow == 0) {
            int col = n0 + wn * 64 + ni * 8 + tcol;
            atomicAdd(&g_sum[col], s0);
            atomicAdd(&g_sum[col + 1], s1);
            atomicAdd(&g_sqs[col], q0);
            atomicAdd(&g_sqs[col + 1], q1);
        }
    }
}

// ---------------- BatchNorm tail ----------------
__global__ void coef_kernel(const float* __restrict__ gamma, const float* __restrict__ beta) {
    int c = blockIdx.x * 256 + threadIdx.x;
    float mu = g_sum[c] * (1.f / B_DIM);
    float var = g_sqs[c] * (1.f / B_DIM) - mu * mu;
    float a = gamma[c] * rsqrtf(var + 1e-5f);
    g_cA[c] = a;
    g_cB[c] = beta[c] - a * mu;
}

// norm: thread owns 8 fixed columns, iterates 64 rows; coeffs hoisted to regs
#define NORM_ROWS 64
__global__ void __launch_bounds__(256) norm_kernel(float* __restrict__ out) {
    const int col = blockIdx.x * 2048 + threadIdx.x * 8;     // 8 halves per thread
    const int row0 = blockIdx.y * NORM_ROWS;

    const float4 a0 = *(const float4*)&g_cA[col];
    const float4 a1 = *(const float4*)&g_cA[col + 4];
    const float4 b0 = *(const float4*)&g_cB[col];
    const float4 b1 = *(const float4*)&g_cB[col + 4];

    const __half* ip = g_o16 + (size_t)row0 * OUT_DIM + col;
    float* op = out + (size_t)row0 * OUT_DIM + col;

#pragma unroll 4
    for (int r = 0; r < NORM_ROWS; r++) {
        uint4 v = *(const uint4*)(ip + (size_t)r * OUT_DIM);
        float2 f0 = __half22float2(*(__half2*)&v.x);
        float2 f1 = __half22float2(*(__half2*)&v.y);
        float2 f2 = __half22float2(*(__half2*)&v.z);
        float2 f3 = __half22float2(*(__half2*)&v.w);
        float4 r0, r1;
        r0.x = fmaf(a0.x, f0.x, b0.x); r0.y = fmaf(a0.y, f0.y, b0.y);
        r0.z = fmaf(a0.z, f1.x, b0.z); r0.w = fmaf(a0.w, f1.y, b0.w);
        r1.x = fmaf(a1.x, f2.x, b1.x); r1.y = fmaf(a1.y, f2.y, b1.y);
        r1.z = fmaf(a1.z, f3.x, b1.z); r1.w = fmaf(a1.w, f3.y, b1.w);
        float* po = op + (size_t)r * OUT_DIM;
        *(float4*)po = r0;
        *(float4*)(po + 4) = r1;
    }
}

extern "C" void kernel_launch(void* const* d_in, const int* in_sizes, int n_in,
                              void* d_out, int out_size) {
    (void)in_sizes; (void)n_in; (void)out_size;
    const float* x     = (const float*)d_in[0];
    const float* w     = (const float*)d_in[1];
    const float* gamma = (const float*)d_in[3];
    const float* beta  = (const float*)d_in[4];
    float* out = (float*)d_out;

    cudaFuncSetAttribute(gemm_kernel, cudaFuncAttributeMaxDynamicSharedMemorySize, GEMM_SMEM);

    cvt_all_kernel<<<XBLOCKS + WBLOCKS, 256>>>(x, w);
    gemm_kernel<<<dim3(B_DIM / TM, OUT_DIM / TN), 256, GEMM_SMEM>>>();
    coef_kernel<<<16, 256>>>(gamma, beta);
    norm_kernel<<<dim3(2, B_DIM / NORM_ROWS), 256>>>(out);
}

// round 15
// speedup vs baseline: 1.0308x; 1.0018x over previous
#include <cuda_runtime.h>
#include <cuda_fp16.h>
#include <cstdint>
#include <cstddef>

#define B_DIM   8192
#define IN_DIM  4096
#define OUT_DIM 4096

// static device scratch (runtime allocation forbidden)
__device__ __align__(16) __half g_x16[(size_t)B_DIM * IN_DIM];
__device__ __align__(16) __half g_w16[(size_t)OUT_DIM * IN_DIM];
__device__ __align__(16) __half g_o16[(size_t)B_DIM * OUT_DIM];
__device__ __align__(16) float  g_sum[OUT_DIM];
__device__ __align__(16) float  g_sqs[OUT_DIM];
__device__ __align__(16) float  g_cA[OUT_DIM];
__device__ __align__(16) float  g_cB[OUT_DIM];

// ---------------- GEMM config ----------------
#define TM 128
#define TN 256
#define TK 64
#define NSTAGE 4
#define KITERS (IN_DIM / TK)        // 64
#define A_STG (TM * 128)            // 16 KB
#define B_STG (TN * 128)            // 32 KB
#define STG_BYTES (A_STG + B_STG)   // 48 KB
#define GEMM_SMEM (NSTAGE * STG_BYTES)  // 192 KB

__device__ __forceinline__ uint32_t smem_u32(const void* p) {
    uint32_t r;
    asm("{ .reg .u64 t; cvta.to.shared.u64 t, %1; cvt.u32.u64 %0, t; }" : "=r"(r) : "l"(p));
    return r;
}
__device__ __forceinline__ uint32_t sw128(uint32_t o) { return o ^ ((o >> 3) & 0x70); }

#define CP_ASYNC16(dst, src) \
    asm volatile("cp.async.cg.shared.global [%0], [%1], 16;" :: "r"(dst), "l"(src) : "memory")

__device__ __forceinline__ void ldsm_x4(uint32_t* r, uint32_t addr) {
    asm volatile("ldmatrix.sync.aligned.m8n8.x4.shared.b16 {%0,%1,%2,%3}, [%4];"
                 : "=r"(r[0]), "=r"(r[1]), "=r"(r[2]), "=r"(r[3]) : "r"(addr));
}
__device__ __forceinline__ void mma16816(float* c, const uint32_t* a, const uint32_t* b) {
    asm volatile("mma.sync.aligned.m16n8k16.row.col.f32.f16.f16.f32 "
                 "{%0,%1,%2,%3}, {%4,%5,%6,%7}, {%8,%9}, {%0,%1,%2,%3};"
                 : "+f"(c[0]), "+f"(c[1]), "+f"(c[2]), "+f"(c[3])
                 : "r"(a[0]), "r"(a[1]), "r"(a[2]), "r"(a[3]), "r"(b[0]), "r"(b[1]));
}

// ------------- merged conversion kernel (x -> fp16, W -> sign fp16) ---------
#define XBLOCKS 16384
#define WBLOCKS 8192
__global__ void cvt_all_kernel(const float* __restrict__ x, const float* __restrict__ w) {
    int b = blockIdx.x;
    if (b < XBLOCKS) {
        size_t i = (size_t)b * blockDim.x + threadIdx.x;
        const float4* p = (const float4*)x;
        float4 a = __ldcs(&p[2 * i]), c = __ldcs(&p[2 * i + 1]);
        __half2 h0 = __floats2half2_rn(a.x, a.y), h1 = __floats2half2_rn(a.z, a.w);
        __half2 h2 = __floats2half2_rn(c.x, c.y), h3 = __floats2half2_rn(c.z, c.w);
        uint4 o;
        o.x = *(uint32_t*)&h0; o.y = *(uint32_t*)&h1;
        o.z = *(uint32_t*)&h2; o.w = *(uint32_t*)&h3;
        ((uint4*)g_x16)[i] = o;
    } else {
        size_t i = (size_t)(b - XBLOCKS) * blockDim.x + threadIdx.x;
        if (i < OUT_DIM) { g_sum[i] = 0.f; g_sqs[i] = 0.f; }   // fused stats zeroing
        const float4* p = (const float4*)w;
        float4 a = __ldcs(&p[2 * i]), c = __ldcs(&p[2 * i + 1]);
        float s[8] = {a.x, a.y, a.z, a.w, c.x, c.y, c.z, c.w};
        __half h[8];
#pragma unroll
        for (int k = 0; k < 8; k++) {
            float v = s[k];
            h[k] = __float2half_rn((v > 0.f) ? 1.f : ((v < 0.f) ? -1.f : 0.f));
        }
        uint4 o;
        o.x = *(uint32_t*)&h[0]; o.y = *(uint32_t*)&h[2];
        o.z = *(uint32_t*)&h[4]; o.w = *(uint32_t*)&h[6];
        ((uint4*)g_w16)[i] = o;
    }
}

// --- GEMM: 128x256 CTA, 8 warps (64x64 tiles), cross-iter frag prefetch -----
__global__ void __launch_bounds__(256, 1) gemm_kernel() {
    extern __shared__ char smem[];
    uint32_t sb = smem_u32(smem);
    const int tid = threadIdx.x;
    const int wid = tid >> 5, lid = tid & 31;
    const int wm = wid >> 2, wn = wid & 3;        // 2 x 4 warp grid
    const int m0 = blockIdx.x * TM, n0 = blockIdx.y * TN;

    const __half* gA = g_x16 + (size_t)m0 * IN_DIM;
    const __half* gB = g_w16 + (size_t)n0 * IN_DIM;

    const int ldr = tid >> 3, ldq = tid & 7;

    // flat 12-chunk list per thread: j<4 -> A rows, j>=4 -> B rows
    auto issue_chunk = [&](int c, int j) {
        uint32_t base = sb + (uint32_t)(c & 3) * STG_BYTES;
        if (j < 4) {
            int r = ldr + j * 32;
            CP_ASYNC16(base + sw128((uint32_t)(r * 128 + ldq * 16)),
                       gA + (size_t)c * TK + (size_t)r * IN_DIM + ldq * 8);
        } else {
            int r = ldr + (j - 4) * 32;
            CP_ASYNC16(base + A_STG + sw128((uint32_t)(r * 128 + ldq * 16)),
                       gB + (size_t)c * TK + (size_t)r * IN_DIM + ldq * 8);
        }
    };

#pragma unroll
    for (int c = 0; c < 3; c++) {
#pragma unroll
        for (int j = 0; j < 12; j++) issue_chunk(c, j);
        asm volatile("cp.async.commit_group;" ::: "memory");
    }

    float acc[4][8][4];
#pragma unroll
    for (int mi = 0; mi < 4; mi++)
#pragma unroll
        for (int ni = 0; ni < 8; ni++)
#pragma unroll
            for (int q = 0; q < 4; q++) acc[mi][ni][q] = 0.f;

    const uint32_t a_row_l = (uint32_t)(wm * 64 + (lid & 15));
    const uint32_t a_col_l = (uint32_t)((lid >> 4) * 16);
    const uint32_t b_row_l = (uint32_t)(wn * 64 + (lid & 7) + ((lid >> 4) << 3));
    const uint32_t b_col_l = (uint32_t)(((lid >> 3) & 1) * 16);

    uint32_t aB[2][4][4], bB[2][4][4];

#define LOADFR(buf, ks, ab, bb) do {                                              \
    _Pragma("unroll")                                                             \
    for (int mi = 0; mi < 4; mi++)                                                \
        ldsm_x4(aB[buf][mi], (ab) + sw128((a_row_l + mi * 16) * 128 + a_col_l + (ks) * 32)); \
    _Pragma("unroll")                                                             \
    for (int nb = 0; nb < 4; nb++)                                                \
        ldsm_x4(bB[buf][nb], (bb) + sw128((b_row_l + nb * 16) * 128 + b_col_l + (ks) * 32)); \
} while (0)

#define MMABLK(buf) do {                                                          \
    _Pragma("unroll")                                                             \
    for (int mi = 0; mi < 4; mi++)                                                \
        _Pragma("unroll")                                                         \
        for (int nb = 0; nb < 4; nb++) {                                          \
            mma16816(acc[mi][2 * nb],     aB[buf][mi], &bB[buf][nb][0]);          \
            mma16816(acc[mi][2 * nb + 1], aB[buf][mi], &bB[buf][nb][2]);          \
        }                                                                         \
} while (0)

#define ISSUE3(j0) do {                                                           \
    if (pf) { issue_chunk(c + 3, (j0)); issue_chunk(c + 3, (j0) + 1); issue_chunk(c + 3, (j0) + 2); } \
} while (0)

    // prologue: retire stage 0's fill for ALL threads, make it visible, preload
    // ks=0 fragments. Invariant at each loop head: buf0 holds (c, ks0) frags
    // and stages c, c+1 are complete+visible (wait_group 2 after 3 commits).
    asm volatile("cp.async.wait_group 2;" ::: "memory");
    __syncthreads();
    LOADFR(0, 0, sb, sb + A_STG);

    for (int c = 0; c < KITERS; c++) {
        uint32_t ab = sb + (uint32_t)(c & 3) * STG_BYTES;
        uint32_t bb = ab + A_STG;
        const bool pf = (c + 3 < KITERS);

        LOADFR(1, 1, ab, bb); MMABLK(0); ISSUE3(0);
        LOADFR(0, 2, ab, bb); MMABLK(1); ISSUE3(3);
        LOADFR(1, 3, ab, bb); MMABLK(0); ISSUE3(6);
        ISSUE3(9);
        asm volatile("cp.async.commit_group;" ::: "memory");

        // retire so that stage c+1 is complete for EVERY thread, then barrier
        // makes it visible; preloading (c+1, ks0) frags is now race-free.
        asm volatile("cp.async.wait_group 2;" ::: "memory");
        __syncthreads();
        if (c + 1 < KITERS) {
            uint32_t an = sb + (uint32_t)((c + 1) & 3) * STG_BYTES;
            LOADFR(0, 0, an, an + A_STG);
        }
        MMABLK(1);   // last k16 of iter c, covers the prefetch latency
    }
#undef LOADFR
#undef MMABLK
#undef ISSUE3

    // ---- epilogue: fp16 store + fused column stats (fp32) ----
    const int trow = lid >> 2, tcol = (lid & 3) * 2;
#pragma unroll
    for (int mi = 0; mi < 4; mi++) {
#pragma unroll
        for (int ni = 0; ni < 8; ni++) {
            int row = m0 + wm * 64 + mi * 16 + trow;
            int col = n0 + wn * 64 + ni * 8 + tcol;
            __half* p = g_o16 + (size_t)row * OUT_DIM + col;
            *(__half2*)p = __floats2half2_rn(acc[mi][ni][0], acc[mi][ni][1]);
            *(__half2*)(p + 8 * OUT_DIM) = __floats2half2_rn(acc[mi][ni][2], acc[mi][ni][3]);
        }
    }
#pragma unroll
    for (int ni = 0; ni < 8; ni++) {
        float s0 = 0.f, s1 = 0.f, q0 = 0.f, q1 = 0.f;
#pragma unroll
        for (int mi = 0; mi < 4; mi++) {
            float v0 = acc[mi][ni][0], v1 = acc[mi][ni][1];
            float v2 = acc[mi][ni][2], v3 = acc[mi][ni][3];
            s0 += v0 + v2; s1 += v1 + v3;
            q0 += v0 * v0 + v2 * v2; q1 += v1 * v1 + v3 * v3;
        }
#pragma unroll
        for (int off = 4; off < 32; off <<= 1) {
            s0 += __shfl_xor_sync(0xffffffffu, s0, off);
            s1 += __shfl_xor_sync(0xffffffffu, s1, off);
            q0 += __shfl_xor_sync(0xffffffffu, q0, off);
            q1 += __shfl_xor_sync(0xffffffffu, q1, off);
        }
        if (trow == 0) {
            int col = n0 + wn * 64 + ni * 8 + tcol;
            atomicAdd(&g_sum[col], s0);
            atomicAdd(&g_sum[col + 1], s1);
            atomicAdd(&g_sqs[col], q0);
            atomicAdd(&g_sqs[col + 1], q1);
        }
    }
}

// ---------------- BatchNorm tail ----------------
__global__ void coef_kernel(const float* __restrict__ gamma, const float* __restrict__ beta) {
    int c = blockIdx.x * 256 + threadIdx.x;
    float mu = g_sum[c] * (1.f / B_DIM);
    float var = g_sqs[c] * (1.f / B_DIM) - mu * mu;
    float a = gamma[c] * rsqrtf(var + 1e-5f);
    g_cA[c] = a;
    g_cB[c] = beta[c] - a * mu;
}

// norm: thread owns 8 fixed columns, iterates 16 rows; coeffs hoisted to regs
#define NORM_ROWS 16
__global__ void __launch_bounds__(256) norm_kernel(float* __restrict__ out) {
    const int col = blockIdx.x * 2048 + threadIdx.x * 8;     // 8 halves per thread
    const int row0 = blockIdx.y * NORM_ROWS;

    const float4 a0 = *(const float4*)&g_cA[col];
    const float4 a1 = *(const float4*)&g_cA[col + 4];
    const float4 b0 = *(const float4*)&g_cB[col];
    const float4 b1 = *(const float4*)&g_cB[col + 4];

    const __half* ip = g_o16 + (size_t)row0 * OUT_DIM + col;
    float* op = out + (size_t)row0 * OUT_DIM + col;

#pragma unroll 4
    for (int r = 0; r < NORM_ROWS; r++) {
        uint4 v = *(const uint4*)(ip + (size_t)r * OUT_DIM);
        float2 f0 = __half22float2(*(__half2*)&v.x);
        float2 f1 = __half22float2(*(__half2*)&v.y);
        float2 f2 = __half22float2(*(__half2*)&v.z);
        float2 f3 = __half22float2(*(__half2*)&v.w);
        float4 r0, r1;
        r0.x = fmaf(a0.x, f0.x, b0.x); r0.y = fmaf(a0.y, f0.y, b0.y);
        r0.z = fmaf(a0.z, f1.x, b0.z); r0.w = fmaf(a0.w, f1.y, b0.w);
        r1.x = fmaf(a1.x, f2.x, b1.x); r1.y = fmaf(a1.y, f2.y, b1.y);
        r1.z = fmaf(a1.z, f3.x, b1.z); r1.w = fmaf(a1.w, f3.y, b1.w);
        float* po = op + (size_t)r * OUT_DIM;
        *(float4*)po = r0;
        *(float4*)(po + 4) = r1;
    }
}

extern "C" void kernel_launch(void* const* d_in, const int* in_sizes, int n_in,
                              void* d_out, int out_size) {
    (void)in_sizes; (void)n_in; (void)out_size;
    const float* x     = (const float*)d_in[0];
    const float* w     = (const float*)d_in[1];
    const float* gamma = (const float*)d_in[3];
    const float* beta  = (const float*)d_in[4];
    float* out = (float*)d_out;

    cudaFuncSetAttribute(gemm_kernel, cudaFuncAttributeMaxDynamicSharedMemorySize, GEMM_SMEM);

    cvt_all_kernel<<<XBLOCKS + WBLOCKS, 256>>>(x, w);
    gemm_kernel<<<dim3(B_DIM / TM, OUT_DIM / TN), 256, GEMM_SMEM>>>();
    coef_kernel<<<16, 256>>>(gamma, beta);
    norm_kernel<<<dim3(2, B_DIM / NORM_ROWS), 256>>>(out);
}